// round 6
// baseline (speedup 1.0000x reference)
#include <cuda_runtime.h>

#define BATCH  32
#define IMG_H  512
#define IMG_W  512
#define TILES  8
#define TSZ    64          // 512 / 8
#define NBINS  256
#define NT     (BATCH * TILES * TILES)   // 2048 tiles
#define PLANE  (IMG_H * IMG_W)           // 262144
#define CLIPV  640                        // floor(40.0 * 4096 / 256)

// XLA rewrites x/const -> x * (1/const). Replicate with the same f32 constants.
#define INV255 (1.0f / 255.0f)
#define INV60  (1.0f / 60.0f)

// Scratch (static device globals — no allocation in kernel_launch)
__device__ unsigned int  g_hls[BATCH * PLANE];    // packed H | L<<8 | S<<16   (33.5 MB)
__device__ unsigned char g_lut[NT * NBINS];       // per-tile LUTs             (512 KB)

// IEEE ops, no FMA contraction (match XLA elementwise emission)
__device__ __forceinline__ float fdiv(float a, float b) { return __fdiv_rn(a, b); }
__device__ __forceinline__ float fmul(float a, float b) { return __fmul_rn(a, b); }
__device__ __forceinline__ float fadd(float a, float b) { return __fadd_rn(a, b); }
__device__ __forceinline__ float fsub(float a, float b) { return __fsub_rn(a, b); }

__device__ __forceinline__ unsigned hls_pixel(float rq, float gq, float bq, int* L8out)
{
    // inputs already clip(floor(v),0,255); x = q * (1/255)
    float r  = fmul(rq, INV255);
    float g  = fmul(gq, INV255);
    float bl = fmul(bq, INV255);

    float vmax = fmaxf(fmaxf(r, g), bl);
    float vmin = fminf(fminf(r, g), bl);
    float l    = fmul(fadd(vmax, vmin), 0.5f);
    float diff = fsub(vmax, vmin);
    float denom = (l < 0.5f) ? fadd(vmax, vmin) : fsub(fsub(2.0f, vmax), vmin);
    float s    = (diff > 0.f) ? fdiv(diff, fmaxf(denom, 1e-12f)) : 0.f;
    float safe = fmaxf(diff, 1e-12f);

    float h;
    if (vmax == r)      h = fdiv(fmul(60.f, fsub(g, bl)), safe);
    else if (vmax == g) h = fadd(120.f, fdiv(fmul(60.f, fsub(bl, r)), safe));
    else                h = fadd(240.f, fdiv(fmul(60.f, fsub(r, g)), safe));
    if (!(diff > 0.f))  h = 0.f;
    if (h < 0.f)        h = fadd(h, 360.f);

    int H8 = (int)fminf(fmaxf(rintf(fmul(h, 0.5f)),  0.f), 255.f);
    int L8 = (int)fminf(fmaxf(rintf(fmul(l, 255.f)), 0.f), 255.f);
    int S8 = (int)fminf(fmaxf(rintf(fmul(s, 255.f)), 0.f), 255.f);

    *L8out = L8;
    return (unsigned)H8 | ((unsigned)L8 << 8) | ((unsigned)S8 << 16);
}

// ---------------------------------------------------------------------------
// Kernel 1: quantize + RGB->HLS (u8) + per-tile histogram + clip/scan -> LUT.
// One block per tile. float4 loads, uint4 packed HLS stores, fused LUT build.
// ---------------------------------------------------------------------------
__global__ __launch_bounds__(256) void k1_hls_hist_lut(const float* __restrict__ img)
{
    __shared__ int hist[NBINS];
    const int tid = threadIdx.x;
    hist[tid] = 0;
    __syncthreads();

    const int gb = blockIdx.x;            // global tile id: b*64 + ty*8 + tx
    const int b  = gb >> 6;
    const int t  = gb & 63;
    const int ty = t >> 3, tx = t & 7;

    const float4* rp = reinterpret_cast<const float4*>(img + (size_t)b * 3 * PLANE);
    const float4* gp = rp + PLANE / 4;
    const float4* bp = gp + PLANE / 4;
    uint4* hlsp = reinterpret_cast<uint4*>(g_hls) + (size_t)b * (PLANE / 4);

    const int fv   = tid & 15;             // float4 index within tile row (16 per row)
    const int row0 = tid >> 4;             // 0..15

    #pragma unroll
    for (int pass = 0; pass < 4; pass++) {
        const int row  = row0 + pass * 16;
        const int y    = ty * TSZ + row;
        const int idx4 = y * (IMG_W / 4) + tx * (TSZ / 4) + fv;

        float4 r4 = rp[idx4];
        float4 g4 = gp[idx4];
        float4 b4 = bp[idx4];

        // quantize: clip(floor(v), 0, 255)
        r4.x = fminf(fmaxf(floorf(r4.x), 0.f), 255.f);
        r4.y = fminf(fmaxf(floorf(r4.y), 0.f), 255.f);
        r4.z = fminf(fmaxf(floorf(r4.z), 0.f), 255.f);
        r4.w = fminf(fmaxf(floorf(r4.w), 0.f), 255.f);
        g4.x = fminf(fmaxf(floorf(g4.x), 0.f), 255.f);
        g4.y = fminf(fmaxf(floorf(g4.y), 0.f), 255.f);
        g4.z = fminf(fmaxf(floorf(g4.z), 0.f), 255.f);
        g4.w = fminf(fmaxf(floorf(g4.w), 0.f), 255.f);
        b4.x = fminf(fmaxf(floorf(b4.x), 0.f), 255.f);
        b4.y = fminf(fmaxf(floorf(b4.y), 0.f), 255.f);
        b4.z = fminf(fmaxf(floorf(b4.z), 0.f), 255.f);
        b4.w = fminf(fmaxf(floorf(b4.w), 0.f), 255.f);

        int L0, L1, L2, L3;
        uint4 o;
        o.x = hls_pixel(r4.x, g4.x, b4.x, &L0);
        o.y = hls_pixel(r4.y, g4.y, b4.y, &L1);
        o.z = hls_pixel(r4.z, g4.z, b4.z, &L2);
        o.w = hls_pixel(r4.w, g4.w, b4.w, &L3);

        atomicAdd(&hist[L0], 1);
        atomicAdd(&hist[L1], 1);
        atomicAdd(&hist[L2], 1);
        atomicAdd(&hist[L3], 1);

        hlsp[idx4] = o;
    }
    __syncthreads();

    // ---- fused former k2: clip + excess redistribution + scan -> LUT ----
    int h = hist[tid];
    __syncthreads();

    hist[tid] = max(h - CLIPV, 0);
    __syncthreads();
    for (int off = 128; off > 0; off >>= 1) {
        if (tid < off) hist[tid] += hist[tid + off];
        __syncthreads();
    }
    const int excess = hist[0];
    __syncthreads();

    h = min(h, CLIPV) + excess / NBINS;
    const int residual = excess % NBINS;
    const int step = max(NBINS / max(residual, 1), 1);
    if (residual > 0 && (tid % step) == 0 && (tid / step) < residual) h += 1;

    // inclusive scan (Hillis–Steele)
    hist[tid] = h;
    __syncthreads();
    for (int off = 1; off < NBINS; off <<= 1) {
        int v = (tid >= off) ? hist[tid - off] : 0;
        __syncthreads();
        hist[tid] += v;
        __syncthreads();
    }

    // scale = 255/4096 exactly representable; cdf*scale < 2^24 -> exact mul
    float lv = rintf(fmul((float)hist[tid], 255.0f / 4096.0f));
    g_lut[gb * NBINS + tid] = (unsigned char)fminf(fmaxf(lv, 0.f), 255.f);
}

// ---------------------------------------------------------------------------
// Kernel 3: bilinear LUT interpolation + HLS->RGB, 4 px / thread
// ---------------------------------------------------------------------------
__device__ __forceinline__ float hue_fn(float p1, float p2, float h)
{
    // h integer-valued in [-120, 630]; conditional +-360 is bit-exact mod 360
    float m = h;
    if (m < 0.f)      m = fadd(m, 360.f);
    else if (m >= 360.f) m = fsub(m, 360.f);
    float hh = fmul(m, INV60);             // XLA: mod(...)/60 -> mul by 1/60
    float d  = fsub(p2, p1);
    if (hh < 1.f) return fadd(p1, fmul(d, hh));
    if (hh < 3.f) return p2;
    if (hh < 4.f) return fadd(p1, fmul(d, fsub(4.f, hh)));
    return p1;
}

__global__ __launch_bounds__(256) void k3_apply(float* __restrict__ out)
{
    const int gid = blockIdx.x * blockDim.x + threadIdx.x;
    const int p   = gid * 4;
    const int b   = p / PLANE;
    const int rem = p % PLANE;
    const int y   = rem >> 9;
    const int x0  = rem & 511;

    // vertical interp coords (shared by the 4 pixels); /64 exact
    float tyf  = (float)y * (1.0f / TSZ) - 0.5f;
    float ty1f = floorf(tyf);
    float ya   = tyf - ty1f;
    int ty1 = (int)ty1f;
    int ty2 = min(ty1 + 1, TILES - 1);
    ty1 = max(ty1, 0);

    const unsigned char* __restrict__ lutb = g_lut + (size_t)b * TILES * TILES * NBINS;

    const uint4 hls4 = *reinterpret_cast<const uint4*>(&g_hls[(size_t)b * PLANE + rem]);
    const unsigned vals[4] = { hls4.x, hls4.y, hls4.z, hls4.w };

    float ro[4], go[4], bo[4];
    #pragma unroll
    for (int j = 0; j < 4; j++) {
        const int x = x0 + j;
        const unsigned pk = vals[j];
        const int H8 = pk & 255, L8 = (pk >> 8) & 255, S8 = (pk >> 16) & 255;

        float txf  = (float)x * (1.0f / TSZ) - 0.5f;
        float tx1f = floorf(txf);
        float xa   = txf - tx1f;
        int tx1 = (int)tx1f;
        int tx2 = min(tx1 + 1, TILES - 1);
        tx1 = max(tx1, 0);

        float g00 = lutb[(ty1 * TILES + tx1) * NBINS + L8];
        float g01 = lutb[(ty1 * TILES + tx2) * NBINS + L8];
        float g10 = lutb[(ty2 * TILES + tx1) * NBINS + L8];
        float g11 = lutb[(ty2 * TILES + tx2) * NBINS + L8];

        // All terms exactly representable -> exact under any op order.
        float res = g00 * (1.f - xa) * (1.f - ya) + g01 * xa * (1.f - ya)
                  + g10 * (1.f - xa) * ya         + g11 * xa * ya;
        float Lnew = fminf(fmaxf(rintf(res), 0.f), 255.f);

        // HLS -> RGB (reciprocal-mul for /255, no FMA contraction)
        float hd = (float)H8 * 2.0f;
        float l  = fmul(Lnew, INV255);
        float s  = fmul((float)S8, INV255);
        float p2 = (l <= 0.5f) ? fmul(l, fadd(1.f, s))
                               : fsub(fadd(l, s), fmul(l, s));
        float p1 = fsub(fmul(2.f, l), p2);

        float r  = hue_fn(p1, p2, hd + 120.f);
        float g  = hue_fn(p1, p2, hd);
        float bb = hue_fn(p1, p2, hd - 120.f);
        if (!(s > 0.f)) { r = l; g = l; bb = l; }

        ro[j] = fminf(fmaxf(rintf(fmul(r,  255.f)), 0.f), 255.f);
        go[j] = fminf(fmaxf(rintf(fmul(g,  255.f)), 0.f), 255.f);
        bo[j] = fminf(fmaxf(rintf(fmul(bb, 255.f)), 0.f), 255.f);
    }

    float* op = out + (size_t)b * 3 * PLANE + rem;
    *reinterpret_cast<float4*>(op)             = make_float4(ro[0], ro[1], ro[2], ro[3]);
    *reinterpret_cast<float4*>(op + PLANE)     = make_float4(go[0], go[1], go[2], go[3]);
    *reinterpret_cast<float4*>(op + 2 * PLANE) = make_float4(bo[0], bo[1], bo[2], bo[3]);
}

// ---------------------------------------------------------------------------
extern "C" void kernel_launch(void* const* d_in, const int* in_sizes, int n_in,
                              void* d_out, int out_size)
{
    (void)in_sizes; (void)n_in; (void)out_size;
    const float* img = (const float*)d_in[0];
    float* out = (float*)d_out;

    k1_hls_hist_lut<<<NT, 256>>>(img);
    k3_apply<<<(BATCH * PLANE / 4) / 256, 256>>>(out);
}

// round 7
// speedup vs baseline: 1.0026x; 1.0026x over previous
#include <cuda_runtime.h>

#define BATCH  32
#define IMG_H  512
#define IMG_W  512
#define TILES  8
#define TSZ    64          // 512 / 8
#define NBINS  256
#define NT     (BATCH * TILES * TILES)   // 2048 tiles
#define PLANE  (IMG_H * IMG_W)           // 262144
#define CLIPV  640                        // floor(40.0 * 4096 / 256)

// XLA rewrites x/const -> x * (1/const). Replicate with the same f32 constants.
#define INV255 (1.0f / 255.0f)
#define INV60  (1.0f / 60.0f)

// Scratch (static device globals — no allocation in kernel_launch)
__device__ unsigned int  g_hls[BATCH * PLANE];    // packed H | L<<8 | S<<16   (33.5 MB)
__device__ unsigned char g_lut[NT * NBINS];       // per-tile LUTs             (512 KB)

// IEEE ops, no FMA contraction (match XLA elementwise emission)
__device__ __forceinline__ float fdiv(float a, float b) { return __fdiv_rn(a, b); }
__device__ __forceinline__ float fmul(float a, float b) { return __fmul_rn(a, b); }
__device__ __forceinline__ float fadd(float a, float b) { return __fadd_rn(a, b); }
__device__ __forceinline__ float fsub(float a, float b) { return __fsub_rn(a, b); }

__device__ __forceinline__ unsigned hls_pixel(float rq, float gq, float bq, int* L8out)
{
    // inputs already clip(floor(v),0,255); x = q * (1/255)
    float r  = fmul(rq, INV255);
    float g  = fmul(gq, INV255);
    float bl = fmul(bq, INV255);

    float vmax = fmaxf(fmaxf(r, g), bl);
    float vmin = fminf(fminf(r, g), bl);
    float l    = fmul(fadd(vmax, vmin), 0.5f);
    float diff = fsub(vmax, vmin);
    float denom = (l < 0.5f) ? fadd(vmax, vmin) : fsub(fsub(2.0f, vmax), vmin);
    float s    = (diff > 0.f) ? fdiv(diff, fmaxf(denom, 1e-12f)) : 0.f;
    float safe = fmaxf(diff, 1e-12f);

    float h;
    if (vmax == r)      h = fdiv(fmul(60.f, fsub(g, bl)), safe);
    else if (vmax == g) h = fadd(120.f, fdiv(fmul(60.f, fsub(bl, r)), safe));
    else                h = fadd(240.f, fdiv(fmul(60.f, fsub(r, g)), safe));
    if (!(diff > 0.f))  h = 0.f;
    if (h < 0.f)        h = fadd(h, 360.f);

    int H8 = (int)fminf(fmaxf(rintf(fmul(h, 0.5f)),  0.f), 255.f);
    int L8 = (int)fminf(fmaxf(rintf(fmul(l, 255.f)), 0.f), 255.f);
    int S8 = (int)fminf(fmaxf(rintf(fmul(s, 255.f)), 0.f), 255.f);

    *L8out = L8;
    return (unsigned)H8 | ((unsigned)L8 << 8) | ((unsigned)S8 << 16);
}

// ---------------------------------------------------------------------------
// Kernel 1: quantize + RGB->HLS (u8) + per-tile histogram + clip/scan -> LUT.
// One block per tile. float4 loads, uint4 packed HLS stores, fused LUT build.
// ---------------------------------------------------------------------------
__global__ __launch_bounds__(256) void k1_hls_hist_lut(const float* __restrict__ img)
{
    __shared__ int hist[NBINS];
    const int tid = threadIdx.x;
    hist[tid] = 0;
    __syncthreads();

    const int gb = blockIdx.x;            // global tile id: b*64 + ty*8 + tx
    const int b  = gb >> 6;
    const int t  = gb & 63;
    const int ty = t >> 3, tx = t & 7;

    const float4* rp = reinterpret_cast<const float4*>(img + (size_t)b * 3 * PLANE);
    const float4* gp = rp + PLANE / 4;
    const float4* bp = gp + PLANE / 4;
    uint4* hlsp = reinterpret_cast<uint4*>(g_hls) + (size_t)b * (PLANE / 4);

    const int fv   = tid & 15;             // float4 index within tile row (16 per row)
    const int row0 = tid >> 4;             // 0..15

    #pragma unroll
    for (int pass = 0; pass < 4; pass++) {
        const int row  = row0 + pass * 16;
        const int y    = ty * TSZ + row;
        const int idx4 = y * (IMG_W / 4) + tx * (TSZ / 4) + fv;

        float4 r4 = rp[idx4];
        float4 g4 = gp[idx4];
        float4 b4 = bp[idx4];

        // quantize: clip(floor(v), 0, 255)
        r4.x = fminf(fmaxf(floorf(r4.x), 0.f), 255.f);
        r4.y = fminf(fmaxf(floorf(r4.y), 0.f), 255.f);
        r4.z = fminf(fmaxf(floorf(r4.z), 0.f), 255.f);
        r4.w = fminf(fmaxf(floorf(r4.w), 0.f), 255.f);
        g4.x = fminf(fmaxf(floorf(g4.x), 0.f), 255.f);
        g4.y = fminf(fmaxf(floorf(g4.y), 0.f), 255.f);
        g4.z = fminf(fmaxf(floorf(g4.z), 0.f), 255.f);
        g4.w = fminf(fmaxf(floorf(g4.w), 0.f), 255.f);
        b4.x = fminf(fmaxf(floorf(b4.x), 0.f), 255.f);
        b4.y = fminf(fmaxf(floorf(b4.y), 0.f), 255.f);
        b4.z = fminf(fmaxf(floorf(b4.z), 0.f), 255.f);
        b4.w = fminf(fmaxf(floorf(b4.w), 0.f), 255.f);

        int L0, L1, L2, L3;
        uint4 o;
        o.x = hls_pixel(r4.x, g4.x, b4.x, &L0);
        o.y = hls_pixel(r4.y, g4.y, b4.y, &L1);
        o.z = hls_pixel(r4.z, g4.z, b4.z, &L2);
        o.w = hls_pixel(r4.w, g4.w, b4.w, &L3);

        atomicAdd(&hist[L0], 1);
        atomicAdd(&hist[L1], 1);
        atomicAdd(&hist[L2], 1);
        atomicAdd(&hist[L3], 1);

        hlsp[idx4] = o;
    }
    __syncthreads();

    // ---- fused former k2: clip + excess redistribution + scan -> LUT ----
    int h = hist[tid];
    __syncthreads();

    hist[tid] = max(h - CLIPV, 0);
    __syncthreads();
    for (int off = 128; off > 0; off >>= 1) {
        if (tid < off) hist[tid] += hist[tid + off];
        __syncthreads();
    }
    const int excess = hist[0];
    __syncthreads();

    h = min(h, CLIPV) + excess / NBINS;
    const int residual = excess % NBINS;
    const int step = max(NBINS / max(residual, 1), 1);
    if (residual > 0 && (tid % step) == 0 && (tid / step) < residual) h += 1;

    // inclusive scan (Hillis–Steele)
    hist[tid] = h;
    __syncthreads();
    for (int off = 1; off < NBINS; off <<= 1) {
        int v = (tid >= off) ? hist[tid - off] : 0;
        __syncthreads();
        hist[tid] += v;
        __syncthreads();
    }

    // scale = 255/4096 exactly representable; cdf*scale < 2^24 -> exact mul
    float lv = rintf(fmul((float)hist[tid], 255.0f / 4096.0f));
    g_lut[gb * NBINS + tid] = (unsigned char)fminf(fmaxf(lv, 0.f), 255.f);
}

// ---------------------------------------------------------------------------
// Kernel 3: bilinear LUT interpolation + HLS->RGB, 4 px / thread
// ---------------------------------------------------------------------------
__device__ __forceinline__ float hue_fn(float p1, float p2, float h)
{
    // h integer-valued in [-120, 630]; conditional +-360 is bit-exact mod 360
    float m = h;
    if (m < 0.f)      m = fadd(m, 360.f);
    else if (m >= 360.f) m = fsub(m, 360.f);
    float hh = fmul(m, INV60);             // XLA: mod(...)/60 -> mul by 1/60
    float d  = fsub(p2, p1);
    if (hh < 1.f) return fadd(p1, fmul(d, hh));
    if (hh < 3.f) return p2;
    if (hh < 4.f) return fadd(p1, fmul(d, fsub(4.f, hh)));
    return p1;
}

__global__ __launch_bounds__(256) void k3_apply(float* __restrict__ out)
{
    const int gid = blockIdx.x * blockDim.x + threadIdx.x;
    const int p   = gid * 4;
    const int b   = p / PLANE;
    const int rem = p % PLANE;
    const int y   = rem >> 9;
    const int x0  = rem & 511;

    // vertical interp coords (shared by the 4 pixels); /64 exact
    float tyf  = (float)y * (1.0f / TSZ) - 0.5f;
    float ty1f = floorf(tyf);
    float ya   = tyf - ty1f;
    int ty1 = (int)ty1f;
    int ty2 = min(ty1 + 1, TILES - 1);
    ty1 = max(ty1, 0);

    const unsigned char* __restrict__ lutb = g_lut + (size_t)b * TILES * TILES * NBINS;

    const uint4 hls4 = *reinterpret_cast<const uint4*>(&g_hls[(size_t)b * PLANE + rem]);
    const unsigned vals[4] = { hls4.x, hls4.y, hls4.z, hls4.w };

    float ro[4], go[4], bo[4];
    #pragma unroll
    for (int j = 0; j < 4; j++) {
        const int x = x0 + j;
        const unsigned pk = vals[j];
        const int H8 = pk & 255, L8 = (pk >> 8) & 255, S8 = (pk >> 16) & 255;

        float txf  = (float)x * (1.0f / TSZ) - 0.5f;
        float tx1f = floorf(txf);
        float xa   = txf - tx1f;
        int tx1 = (int)tx1f;
        int tx2 = min(tx1 + 1, TILES - 1);
        tx1 = max(tx1, 0);

        float g00 = lutb[(ty1 * TILES + tx1) * NBINS + L8];
        float g01 = lutb[(ty1 * TILES + tx2) * NBINS + L8];
        float g10 = lutb[(ty2 * TILES + tx1) * NBINS + L8];
        float g11 = lutb[(ty2 * TILES + tx2) * NBINS + L8];

        // All terms exactly representable -> exact under any op order.
        float res = g00 * (1.f - xa) * (1.f - ya) + g01 * xa * (1.f - ya)
                  + g10 * (1.f - xa) * ya         + g11 * xa * ya;
        float Lnew = fminf(fmaxf(rintf(res), 0.f), 255.f);

        // HLS -> RGB (reciprocal-mul for /255, no FMA contraction)
        float hd = (float)H8 * 2.0f;
        float l  = fmul(Lnew, INV255);
        float s  = fmul((float)S8, INV255);
        float p2 = (l <= 0.5f) ? fmul(l, fadd(1.f, s))
                               : fsub(fadd(l, s), fmul(l, s));
        float p1 = fsub(fmul(2.f, l), p2);

        float r  = hue_fn(p1, p2, hd + 120.f);
        float g  = hue_fn(p1, p2, hd);
        float bb = hue_fn(p1, p2, hd - 120.f);
        if (!(s > 0.f)) { r = l; g = l; bb = l; }

        ro[j] = fminf(fmaxf(rintf(fmul(r,  255.f)), 0.f), 255.f);
        go[j] = fminf(fmaxf(rintf(fmul(g,  255.f)), 0.f), 255.f);
        bo[j] = fminf(fmaxf(rintf(fmul(bb, 255.f)), 0.f), 255.f);
    }

    float* op = out + (size_t)b * 3 * PLANE + rem;
    *reinterpret_cast<float4*>(op)             = make_float4(ro[0], ro[1], ro[2], ro[3]);
    *reinterpret_cast<float4*>(op + PLANE)     = make_float4(go[0], go[1], go[2], go[3]);
    *reinterpret_cast<float4*>(op + 2 * PLANE) = make_float4(bo[0], bo[1], bo[2], bo[3]);
}

// ---------------------------------------------------------------------------
extern "C" void kernel_launch(void* const* d_in, const int* in_sizes, int n_in,
                              void* d_out, int out_size)
{
    (void)in_sizes; (void)n_in; (void)out_size;
    const float* img = (const float*)d_in[0];
    float* out = (float*)d_out;

    k1_hls_hist_lut<<<NT, 256>>>(img);
    k3_apply<<<(BATCH * PLANE / 4) / 256, 256>>>(out);
}

// round 8
// speedup vs baseline: 1.0892x; 1.0864x over previous
#include <cuda_runtime.h>

#define BATCH  32
#define IMG_H  512
#define IMG_W  512
#define TILES  8
#define TSZ    64          // 512 / 8
#define NBINS  256
#define NT     (BATCH * TILES * TILES)   // 2048 tiles
#define PLANE  (IMG_H * IMG_W)           // 262144
#define CLIPV  640                        // floor(40.0 * 4096 / 256)

// XLA rewrites x/const -> x * (1/const). Replicate with the same f32 constants.
#define INV255 (1.0f / 255.0f)
#define INV60  (1.0f / 60.0f)

// Scratch (static device globals — no allocation in kernel_launch)
__device__ unsigned int   g_hls[BATCH * PLANE];   // packed H | L<<8 | S<<16   (33.5 MB)
__device__ unsigned char  g_lut[NT * NBINS];      // per-tile LUTs             (512 KB)
__device__ unsigned short g_tabLS[65536];         // (qmax,qmin) -> L8|S8<<8   (128 KB)

// IEEE ops, no FMA contraction (match XLA elementwise emission)
__device__ __forceinline__ float fdiv(float a, float b) { return __fdiv_rn(a, b); }
__device__ __forceinline__ float fmul(float a, float b) { return __fmul_rn(a, b); }
__device__ __forceinline__ float fadd(float a, float b) { return __fadd_rn(a, b); }
__device__ __forceinline__ float fsub(float a, float b) { return __fsub_rn(a, b); }

// ---------------------------------------------------------------------------
// Kernel 0: tabulate L8/S8 for all (qmax, qmin) pairs — exact reference ops.
// Recomputed every launch (deterministic). 64K threads, trivial.
// ---------------------------------------------------------------------------
__global__ __launch_bounds__(256) void k0_tab()
{
    const int idx = blockIdx.x * 256 + threadIdx.x;
    const float qmax = (float)(idx >> 8);
    const float qmin = (float)(idx & 255);

    float vmax = fmul(qmax, INV255);
    float vmin = fmul(qmin, INV255);
    float l    = fmul(fadd(vmax, vmin), 0.5f);
    float diff = fsub(vmax, vmin);
    float denom = (l < 0.5f) ? fadd(vmax, vmin) : fsub(fsub(2.0f, vmax), vmin);
    float s    = (diff > 0.f) ? fdiv(diff, fmaxf(denom, 1e-12f)) : 0.f;

    int L8 = (int)fminf(fmaxf(rintf(fmul(l, 255.f)), 0.f), 255.f);
    int S8 = (int)fminf(fmaxf(rintf(fmul(s, 255.f)), 0.f), 255.f);
    g_tabLS[idx] = (unsigned short)(L8 | (S8 << 8));
}

// ---------------------------------------------------------------------------
__device__ __forceinline__ unsigned hls_pixel(float rq, float gq, float bq, int* L8out)
{
    // inputs already clip(floor(v),0,255): exact small integers in float
    float qmaxf = fmaxf(fmaxf(rq, gq), bq);   // == 255*vmax pre-scale (monotone)
    float qminf = fminf(fminf(rq, gq), bq);

    unsigned ls = __ldg(&g_tabLS[((int)qmaxf << 8) | (int)qminf]);
    int L8 = ls & 255, S8 = ls >> 8;

    float h = 0.f;
    if (qmaxf > qminf) {
        // safe = fmaxf(diff,1e-12) == diff here (diff >= ~0.0039 when >0)
        float safe = fsub(fmul(qmaxf, INV255), fmul(qminf, INV255));
        float r  = fmul(rq, INV255);
        float g  = fmul(gq, INV255);
        float bl = fmul(bq, INV255);
        if (rq == qmaxf)      h = fdiv(fmul(60.f, fsub(g, bl)), safe);
        else if (gq == qmaxf) h = fadd(120.f, fdiv(fmul(60.f, fsub(bl, r)), safe));
        else                  h = fadd(240.f, fdiv(fmul(60.f, fsub(r, g)), safe));
        if (h < 0.f) h = fadd(h, 360.f);
    }
    int H8 = (int)fminf(fmaxf(rintf(fmul(h, 0.5f)), 0.f), 255.f);

    *L8out = L8;
    return (unsigned)H8 | ((unsigned)L8 << 8) | ((unsigned)S8 << 16);
}

// ---------------------------------------------------------------------------
// Kernel 1: quantize + RGB->HLS (u8) + per-tile histogram + clip/scan -> LUT.
// One block per tile. float4 streaming loads, uint4 packed HLS stores.
// ---------------------------------------------------------------------------
__global__ __launch_bounds__(256) void k1_hls_hist_lut(const float* __restrict__ img)
{
    __shared__ int hist[NBINS];
    const int tid = threadIdx.x;
    hist[tid] = 0;
    __syncthreads();

    const int gb = blockIdx.x;            // global tile id: b*64 + ty*8 + tx
    const int b  = gb >> 6;
    const int t  = gb & 63;
    const int ty = t >> 3, tx = t & 7;

    const float4* rp = reinterpret_cast<const float4*>(img + (size_t)b * 3 * PLANE);
    const float4* gp = rp + PLANE / 4;
    const float4* bp = gp + PLANE / 4;
    uint4* hlsp = reinterpret_cast<uint4*>(g_hls) + (size_t)b * (PLANE / 4);

    const int fv   = tid & 15;             // float4 index within tile row (16 per row)
    const int row0 = tid >> 4;             // 0..15

    #pragma unroll
    for (int pass = 0; pass < 4; pass++) {
        const int row  = row0 + pass * 16;
        const int y    = ty * TSZ + row;
        const int idx4 = y * (IMG_W / 4) + tx * (TSZ / 4) + fv;

        float4 r4 = __ldcs(&rp[idx4]);     // streaming: don't evict g_tabLS
        float4 g4 = __ldcs(&gp[idx4]);
        float4 b4 = __ldcs(&bp[idx4]);

        // quantize: clip(floor(v), 0, 255)
        r4.x = fminf(fmaxf(floorf(r4.x), 0.f), 255.f);
        r4.y = fminf(fmaxf(floorf(r4.y), 0.f), 255.f);
        r4.z = fminf(fmaxf(floorf(r4.z), 0.f), 255.f);
        r4.w = fminf(fmaxf(floorf(r4.w), 0.f), 255.f);
        g4.x = fminf(fmaxf(floorf(g4.x), 0.f), 255.f);
        g4.y = fminf(fmaxf(floorf(g4.y), 0.f), 255.f);
        g4.z = fminf(fmaxf(floorf(g4.z), 0.f), 255.f);
        g4.w = fminf(fmaxf(floorf(g4.w), 0.f), 255.f);
        b4.x = fminf(fmaxf(floorf(b4.x), 0.f), 255.f);
        b4.y = fminf(fmaxf(floorf(b4.y), 0.f), 255.f);
        b4.z = fminf(fmaxf(floorf(b4.z), 0.f), 255.f);
        b4.w = fminf(fmaxf(floorf(b4.w), 0.f), 255.f);

        int L0, L1, L2, L3;
        uint4 o;
        o.x = hls_pixel(r4.x, g4.x, b4.x, &L0);
        o.y = hls_pixel(r4.y, g4.y, b4.y, &L1);
        o.z = hls_pixel(r4.z, g4.z, b4.z, &L2);
        o.w = hls_pixel(r4.w, g4.w, b4.w, &L3);

        atomicAdd(&hist[L0], 1);
        atomicAdd(&hist[L1], 1);
        atomicAdd(&hist[L2], 1);
        atomicAdd(&hist[L3], 1);

        __stcs(&hlsp[idx4], o);
    }
    __syncthreads();

    // ---- fused: clip + excess redistribution + scan -> LUT ----
    int h = hist[tid];
    __syncthreads();

    hist[tid] = max(h - CLIPV, 0);
    __syncthreads();
    for (int off = 128; off > 0; off >>= 1) {
        if (tid < off) hist[tid] += hist[tid + off];
        __syncthreads();
    }
    const int excess = hist[0];
    __syncthreads();

    h = min(h, CLIPV) + excess / NBINS;
    const int residual = excess % NBINS;
    const int step = max(NBINS / max(residual, 1), 1);
    if (residual > 0 && (tid % step) == 0 && (tid / step) < residual) h += 1;

    // inclusive scan (Hillis–Steele)
    hist[tid] = h;
    __syncthreads();
    for (int off = 1; off < NBINS; off <<= 1) {
        int v = (tid >= off) ? hist[tid - off] : 0;
        __syncthreads();
        hist[tid] += v;
        __syncthreads();
    }

    float lv = rintf(fmul((float)hist[tid], 255.0f / 4096.0f));
    g_lut[gb * NBINS + tid] = (unsigned char)fminf(fmaxf(lv, 0.f), 255.f);
}

// ---------------------------------------------------------------------------
// Kernel 3: integer bilinear LUT interpolation + HLS->RGB, 4 px / thread
// ---------------------------------------------------------------------------
__device__ __forceinline__ float hue_fn(float p1, float p2, float d, int hi)
{
    // hi integer in [-120, 630]; conditional +-360 == fmod for integers (exact)
    if (hi < 0)        hi += 360;
    else if (hi >= 360) hi -= 360;
    float hh = fmul((float)hi, INV60);     // XLA: mod(...)/60 -> mul by 1/60
    if (hh < 1.f) return fadd(p1, fmul(d, hh));
    if (hh < 3.f) return p2;
    if (hh < 4.f) return fadd(p1, fmul(d, fsub(4.f, hh)));
    return p1;
}

__global__ __launch_bounds__(256) void k3_apply(float* __restrict__ out)
{
    const int gid = blockIdx.x * blockDim.x + threadIdx.x;
    const int p   = gid * 4;
    const int b   = p >> 18;               // / PLANE
    const int rem = p & (PLANE - 1);
    const int y   = rem >> 9;
    const int x0  = rem & 511;

    // vertical interp (integer): tyf = (y-32)/64
    const int ym   = y - 32;
    const int ty1s = ym >> 6;               // floor
    const int wy1  = ym & 63;               // ya * 64  (exact, incl. negatives)
    const int wy0  = 64 - wy1;
    const int ty1  = max(ty1s, 0);
    const int ty2  = min(ty1s + 1, TILES - 1);

    const unsigned char* __restrict__ lutb = g_lut + b * (TILES * TILES * NBINS);
    const int tb1 = ty1 << 11;              // ty1 * 8 * 256
    const int tb2 = ty2 << 11;

    const uint4 hls4 = __ldcs(reinterpret_cast<const uint4*>(&g_hls[(size_t)b * PLANE + rem]));
    const unsigned vals[4] = { hls4.x, hls4.y, hls4.z, hls4.w };

    float ro[4], go[4], bo[4];
    #pragma unroll
    for (int j = 0; j < 4; j++) {
        const unsigned pk = vals[j];
        const int H8 = pk & 255, L8 = (pk >> 8) & 255, S8 = (pk >> 16) & 255;

        const int xm   = x0 + j - 32;
        const int tx1s = xm >> 6;
        const int wx1  = xm & 63;
        const int wx0  = 64 - wx1;
        const int tx1  = max(tx1s, 0);
        const int tx2  = min(tx1s + 1, TILES - 1);

        const int c1 = (tx1 << 8) + L8;
        const int c2 = (tx2 << 8) + L8;
        const int g00 = lutb[tb1 + c1];
        const int g01 = lutb[tb1 + c2];
        const int g10 = lutb[tb2 + c1];
        const int g11 = lutb[tb2 + c2];

        // res = sum/4096 exactly (matches fp32 reference sum bit-for-bit);
        // round-half-even in integers.
        const int sum = (g00 * wx0 + g01 * wx1) * wy0 + (g10 * wx0 + g11 * wx1) * wy1;
        const int q   = sum >> 12;
        const int rr  = sum & 4095;
        const int Lnew = q + ((rr > 2048 || (rr == 2048 && (q & 1))) ? 1 : 0);

        // HLS -> RGB (reciprocal-mul for /255, no FMA contraction)
        float l  = fmul((float)Lnew, INV255);
        float s  = fmul((float)S8, INV255);
        float p2 = (l <= 0.5f) ? fmul(l, fadd(1.f, s))
                               : fsub(fadd(l, s), fmul(l, s));
        float p1 = fsub(fmul(2.f, l), p2);
        float d  = fsub(p2, p1);

        const int hi = H8 << 1;             // h = H8 * 2 (exact)
        float r  = hue_fn(p1, p2, d, hi + 120);
        float g  = hue_fn(p1, p2, d, hi);
        float bb = hue_fn(p1, p2, d, hi - 120);
        if (!(s > 0.f)) { r = l; g = l; bb = l; }

        // outputs provably in [0,255] after rint -> clip is a no-op
        ro[j] = rintf(fmul(r,  255.f));
        go[j] = rintf(fmul(g,  255.f));
        bo[j] = rintf(fmul(bb, 255.f));
    }

    float* op = out + (size_t)b * 3 * PLANE + rem;
    *reinterpret_cast<float4*>(op)             = make_float4(ro[0], ro[1], ro[2], ro[3]);
    *reinterpret_cast<float4*>(op + PLANE)     = make_float4(go[0], go[1], go[2], go[3]);
    *reinterpret_cast<float4*>(op + 2 * PLANE) = make_float4(bo[0], bo[1], bo[2], bo[3]);
}

// ---------------------------------------------------------------------------
extern "C" void kernel_launch(void* const* d_in, const int* in_sizes, int n_in,
                              void* d_out, int out_size)
{
    (void)in_sizes; (void)n_in; (void)out_size;
    const float* img = (const float*)d_in[0];
    float* out = (float*)d_out;

    k0_tab<<<256, 256>>>();
    k1_hls_hist_lut<<<NT, 256>>>(img);
    k3_apply<<<(BATCH * PLANE / 4) / 256, 256>>>(out);
}

// round 9
// speedup vs baseline: 1.2633x; 1.1598x over previous
#include <cuda_runtime.h>

#define BATCH  32
#define IMG_H  512
#define IMG_W  512
#define TILES  8
#define TSZ    64          // 512 / 8
#define NBINS  256
#define NT     (BATCH * TILES * TILES)   // 2048 tiles
#define PLANE  (IMG_H * IMG_W)           // 262144
#define CLIPV  640                        // floor(40.0 * 4096 / 256)

// XLA rewrites x/const -> x * (1/const). Replicate with the same f32 constants.
#define INV255 (1.0f / 255.0f)
#define INV60  (1.0f / 60.0f)

// Scratch (static device globals — no allocation in kernel_launch)
__device__ unsigned int   g_hls[BATCH * PLANE];   // packed H | L<<8 | S<<16   (33.5 MB)
__device__ unsigned char  g_lut[NT * NBINS];      // per-tile LUTs             (512 KB)

// ---------------------------------------------------------------------------
// Compile-time (qmax,qmin) -> L8|S8<<8 table. Compile-time fp32 arithmetic is
// correctly-rounded IEEE single — bit-identical to the device __f*_rn ops.
// ---------------------------------------------------------------------------
struct TabPart { unsigned short v[4096]; };

constexpr float crint_nn(float x) {   // round half to even, x in [0, 2^23)
    int t = (int)x;
    float ft = (float)t;
    float frac = x - ft;               // exact (Sterbenz)
    if (frac > 0.5f) return ft + 1.0f;
    if (frac < 0.5f) return ft;
    return (t & 1) ? ft + 1.0f : ft;
}

constexpr TabPart make_part(int part) {
    TabPart tp{};
    for (int i = 0; i < 4096; i++) {
        int idx = part * 4096 + i;
        float qmax = (float)(idx >> 8);
        float qmin = (float)(idx & 255);
        float vmax = qmax * (1.0f / 255.0f);
        float vmin = qmin * (1.0f / 255.0f);
        float l    = (vmax + vmin) * 0.5f;
        float diff = vmax - vmin;
        float denom = (l < 0.5f) ? (vmax + vmin) : ((2.0f - vmax) - vmin);
        float dmax  = (denom > 1e-12f) ? denom : 1e-12f;
        float s     = (diff > 0.0f) ? (diff / dmax) : 0.0f;
        float L = crint_nn(l * 255.0f);
        float S = crint_nn(s * 255.0f);
        if (L > 255.0f) L = 255.0f;  if (L < 0.0f) L = 0.0f;
        if (S > 255.0f) S = 255.0f;  if (S < 0.0f) S = 0.0f;
        tp.v[i] = (unsigned short)((int)L | ((int)S << 8));
    }
    return tp;
}

__device__ const TabPart g_tab16[16] = {
    make_part(0),  make_part(1),  make_part(2),  make_part(3),
    make_part(4),  make_part(5),  make_part(6),  make_part(7),
    make_part(8),  make_part(9),  make_part(10), make_part(11),
    make_part(12), make_part(13), make_part(14), make_part(15)
};

// IEEE ops, no FMA contraction (match XLA elementwise emission)
__device__ __forceinline__ float fdiv(float a, float b) { return __fdiv_rn(a, b); }
__device__ __forceinline__ float fmul(float a, float b) { return __fmul_rn(a, b); }
__device__ __forceinline__ float fadd(float a, float b) { return __fadd_rn(a, b); }
__device__ __forceinline__ float fsub(float a, float b) { return __fsub_rn(a, b); }

// ---------------------------------------------------------------------------
__device__ __forceinline__ unsigned hls_pixel(float rq, float gq, float bq, int* L8out)
{
    // inputs already clip(floor(v),0,255): exact small integers in float
    float qmaxf = fmaxf(fmaxf(rq, gq), bq);   // scaling is monotone-injective
    float qminf = fminf(fminf(rq, gq), bq);

    const unsigned short* tab = reinterpret_cast<const unsigned short*>(g_tab16);
    unsigned ls = __ldg(&tab[((int)qmaxf << 8) | (int)qminf]);
    int L8 = ls & 255, S8 = ls >> 8;

    float r  = fmul(rq, INV255);
    float g  = fmul(gq, INV255);
    float bl = fmul(bq, INV255);
    // safe = fmaxf(diff,1e-12) == diff whenever diff > 0 (min diff ~0.0039)
    float safe = fsub(fmul(qmaxf, INV255), fmul(qminf, INV255));

    const bool isr = (rq == qmaxf);
    const bool isg = (gq == qmaxf);
    float num = isr ? fsub(g, bl) : (isg ? fsub(bl, r) : fsub(r, g));
    float off = isr ? 0.f : (isg ? 120.f : 240.f);
    // gray pixels: 0/0 = NaN, selected away (reference forces h=0 when diff<=0)
    float h = (qmaxf > qminf) ? fadd(off, fdiv(fmul(60.f, num), safe)) : 0.f;
    if (h < 0.f) h = fadd(h, 360.f);

    int H8 = (int)fminf(fmaxf(rintf(fmul(h, 0.5f)), 0.f), 255.f);
    *L8out = L8;
    return (unsigned)H8 | ((unsigned)L8 << 8) | ((unsigned)S8 << 16);
}

// ---------------------------------------------------------------------------
// Kernel 1: quantize + RGB->HLS (u8) + per-tile histogram + clip/scan -> LUT.
// One block per tile. float4 streaming loads, uint4 packed HLS stores.
// ---------------------------------------------------------------------------
__global__ __launch_bounds__(256) void k1_hls_hist_lut(const float* __restrict__ img)
{
    __shared__ int hist[NBINS];
    const int tid = threadIdx.x;
    hist[tid] = 0;
    __syncthreads();

    const int gb = blockIdx.x;            // global tile id: b*64 + ty*8 + tx
    const int b  = gb >> 6;
    const int t  = gb & 63;
    const int ty = t >> 3, tx = t & 7;

    const float4* rp = reinterpret_cast<const float4*>(img + (size_t)b * 3 * PLANE);
    const float4* gp = rp + PLANE / 4;
    const float4* bp = gp + PLANE / 4;
    uint4* hlsp = reinterpret_cast<uint4*>(g_hls) + (size_t)b * (PLANE / 4);

    const int fv   = tid & 15;             // float4 index within tile row (16 per row)
    const int row0 = tid >> 4;             // 0..15

    #pragma unroll
    for (int pass = 0; pass < 4; pass++) {
        const int row  = row0 + pass * 16;
        const int y    = ty * TSZ + row;
        const int idx4 = y * (IMG_W / 4) + tx * (TSZ / 4) + fv;

        float4 r4 = __ldcs(&rp[idx4]);     // streaming: don't evict the table
        float4 g4 = __ldcs(&gp[idx4]);
        float4 b4 = __ldcs(&bp[idx4]);

        // quantize: clip(floor(v), 0, 255)
        r4.x = fminf(fmaxf(floorf(r4.x), 0.f), 255.f);
        r4.y = fminf(fmaxf(floorf(r4.y), 0.f), 255.f);
        r4.z = fminf(fmaxf(floorf(r4.z), 0.f), 255.f);
        r4.w = fminf(fmaxf(floorf(r4.w), 0.f), 255.f);
        g4.x = fminf(fmaxf(floorf(g4.x), 0.f), 255.f);
        g4.y = fminf(fmaxf(floorf(g4.y), 0.f), 255.f);
        g4.z = fminf(fmaxf(floorf(g4.z), 0.f), 255.f);
        g4.w = fminf(fmaxf(floorf(g4.w), 0.f), 255.f);
        b4.x = fminf(fmaxf(floorf(b4.x), 0.f), 255.f);
        b4.y = fminf(fmaxf(floorf(b4.y), 0.f), 255.f);
        b4.z = fminf(fmaxf(floorf(b4.z), 0.f), 255.f);
        b4.w = fminf(fmaxf(floorf(b4.w), 0.f), 255.f);

        int L0, L1, L2, L3;
        uint4 o;
        o.x = hls_pixel(r4.x, g4.x, b4.x, &L0);
        o.y = hls_pixel(r4.y, g4.y, b4.y, &L1);
        o.z = hls_pixel(r4.z, g4.z, b4.z, &L2);
        o.w = hls_pixel(r4.w, g4.w, b4.w, &L3);

        atomicAdd(&hist[L0], 1);
        atomicAdd(&hist[L1], 1);
        atomicAdd(&hist[L2], 1);
        atomicAdd(&hist[L3], 1);

        __stcs(&hlsp[idx4], o);
    }
    __syncthreads();

    // ---- fused: clip + excess redistribution + scan -> LUT ----
    int h = hist[tid];
    __syncthreads();

    hist[tid] = max(h - CLIPV, 0);
    __syncthreads();
    for (int off = 128; off > 0; off >>= 1) {
        if (tid < off) hist[tid] += hist[tid + off];
        __syncthreads();
    }
    const int excess = hist[0];
    __syncthreads();

    h = min(h, CLIPV) + excess / NBINS;
    const int residual = excess % NBINS;
    const int step = max(NBINS / max(residual, 1), 1);
    if (residual > 0 && (tid % step) == 0 && (tid / step) < residual) h += 1;

    // inclusive scan (Hillis–Steele)
    hist[tid] = h;
    __syncthreads();
    for (int off = 1; off < NBINS; off <<= 1) {
        int v = (tid >= off) ? hist[tid - off] : 0;
        __syncthreads();
        hist[tid] += v;
        __syncthreads();
    }

    float lv = rintf(fmul((float)hist[tid], 255.0f / 4096.0f));
    g_lut[gb * NBINS + tid] = (unsigned char)fminf(fmaxf(lv, 0.f), 255.f);
}

// ---------------------------------------------------------------------------
// Kernel 3: bilinear LUT interp (smem-staged LUTs) + HLS->RGB, 4 px / thread.
// Each block = 2 image rows (1024 px); an (even,odd) row pair always shares
// one (ty1,ty2) pair, so the block needs exactly 16 LUTs = 4 KB.
// ---------------------------------------------------------------------------
__device__ __forceinline__ float hue_fn(float p1, float p2, float d, int hi)
{
    // hi integer in [-120, 630]; conditional +-360 == fmod for integers (exact)
    if (hi < 0)         hi += 360;
    else if (hi >= 360) hi -= 360;
    float hh = fmul((float)hi, INV60);     // XLA: mod(...)/60 -> mul by 1/60
    if (hh < 1.f) return fadd(p1, fmul(d, hh));
    if (hh < 3.f) return p2;
    if (hh < 4.f) return fadd(p1, fmul(d, fsub(4.f, hh)));
    return p1;
}

__global__ __launch_bounds__(256) void k3_apply(float* __restrict__ out)
{
    __shared__ unsigned char lutS[4096];   // [2 rows][8 tiles][256 bins]
    const int blk  = blockIdx.x;
    const int b    = blk >> 8;             // 256 blocks per image
    const int rem0 = (blk & 255) << 10;    // segment start (2 rows)
    const int tid  = threadIdx.x;
    const int y0   = rem0 >> 9;            // even row

    const int ty1s = (y0 - 32) >> 6;
    const int ty1  = max(ty1s, 0);
    const int ty2  = min(ty1s + 1, TILES - 1);

    {   // cooperative LUT stage: 1 coalesced uint4 per thread
        const int trow = (tid < 128) ? ty1 : ty2;
        const unsigned char* gsrc = g_lut + b * (TILES * TILES * NBINS)
                                  + (trow << 11) + ((tid & 127) << 4);
        reinterpret_cast<uint4*>(lutS)[tid] = *reinterpret_cast<const uint4*>(gsrc);
    }
    __syncthreads();

    const int y   = y0 + (tid >> 7);        // threads 0-127: row y0; 128-255: y0+1
    const int wy1 = (y - 32) & 63;          // ya * 64 (exact)
    const int wy0 = 64 - wy1;
    const int x0  = (tid << 2) & 511;
    const int rem = rem0 + tid * 4;

    const uint4 hls4 = __ldcs(reinterpret_cast<const uint4*>(&g_hls[(size_t)b * PLANE + rem]));
    const unsigned vals[4] = { hls4.x, hls4.y, hls4.z, hls4.w };

    float ro[4], go[4], bo[4];
    #pragma unroll
    for (int j = 0; j < 4; j++) {
        const unsigned pk = vals[j];
        const int H8 = pk & 255, L8 = (pk >> 8) & 255, S8 = (pk >> 16) & 255;

        const int xm   = x0 + j - 32;
        const int tx1s = xm >> 6;
        const int wx1  = xm & 63;
        const int wx0  = 64 - wx1;
        const int tx1  = max(tx1s, 0);
        const int tx2  = min(tx1s + 1, TILES - 1);

        const int c1 = (tx1 << 8) + L8;
        const int c2 = (tx2 << 8) + L8;
        const int g00 = lutS[c1];
        const int g01 = lutS[c2];
        const int g10 = lutS[2048 + c1];
        const int g11 = lutS[2048 + c2];

        // sum/4096 == fp32 reference bilinear exactly; sum < 2^21 so the
        // cvt + mul-by-2^-12 are exact and rintf gives half-even ties.
        const int sum = (g00 * wx0 + g01 * wx1) * wy0 + (g10 * wx0 + g11 * wx1) * wy1;
        const float Lnewf = rintf((float)sum * (1.0f / 4096.0f));

        // HLS -> RGB (reciprocal-mul for /255, no FMA contraction)
        float l  = fmul(Lnewf, INV255);
        float s  = fmul((float)S8, INV255);
        float p2 = (l <= 0.5f) ? fmul(l, fadd(1.f, s))
                               : fsub(fadd(l, s), fmul(l, s));
        float p1 = fsub(fmul(2.f, l), p2);
        float d  = fsub(p2, p1);

        const int hi = H8 << 1;              // h = H8 * 2 (exact)
        float r  = hue_fn(p1, p2, d, hi + 120);
        float g  = hue_fn(p1, p2, d, hi);
        float bb = hue_fn(p1, p2, d, hi - 120);
        if (!(s > 0.f)) { r = l; g = l; bb = l; }

        // outputs provably in [0,255] after rint -> clip is a no-op
        ro[j] = rintf(fmul(r,  255.f));
        go[j] = rintf(fmul(g,  255.f));
        bo[j] = rintf(fmul(bb, 255.f));
    }

    float* op = out + (size_t)b * 3 * PLANE + rem;
    *reinterpret_cast<float4*>(op)             = make_float4(ro[0], ro[1], ro[2], ro[3]);
    *reinterpret_cast<float4*>(op + PLANE)     = make_float4(go[0], go[1], go[2], go[3]);
    *reinterpret_cast<float4*>(op + 2 * PLANE) = make_float4(bo[0], bo[1], bo[2], bo[3]);
}

// ---------------------------------------------------------------------------
extern "C" void kernel_launch(void* const* d_in, const int* in_sizes, int n_in,
                              void* d_out, int out_size)
{
    (void)in_sizes; (void)n_in; (void)out_size;
    const float* img = (const float*)d_in[0];
    float* out = (float*)d_out;

    k1_hls_hist_lut<<<NT, 256>>>(img);
    k3_apply<<<BATCH * 256, 256>>>(out);
}

// round 10
// speedup vs baseline: 1.3664x; 1.0817x over previous
#include <cuda_runtime.h>

#define BATCH  32
#define IMG_H  512
#define IMG_W  512
#define TILES  8
#define TSZ    64          // 512 / 8
#define NBINS  256
#define NT     (BATCH * TILES * TILES)   // 2048 tiles
#define PLANE  (IMG_H * IMG_W)           // 262144
#define CLIPV  640                        // floor(40.0 * 4096 / 256)

// XLA rewrites x/const -> x * (1/const). Replicate with the same f32 constants.
#define INV255 (1.0f / 255.0f)
#define INV60  (1.0f / 60.0f)

// Scratch (static device globals — no allocation in kernel_launch)
__device__ unsigned int   g_hls[BATCH * PLANE];   // packed H | L<<8 | S<<16   (33.5 MB)
__device__ unsigned char  g_lut[NT * NBINS];      // per-tile LUTs             (512 KB)

// ---------------------------------------------------------------------------
// Compile-time (qmax,qmin) -> L8|S8<<8 table. Compile-time fp32 arithmetic is
// correctly-rounded IEEE single — bit-identical to the device __f*_rn ops.
// ---------------------------------------------------------------------------
struct TabPart { unsigned short v[4096]; };

constexpr float crint_nn(float x) {   // round half to even, x in [0, 2^23)
    int t = (int)x;
    float ft = (float)t;
    float frac = x - ft;               // exact (Sterbenz)
    if (frac > 0.5f) return ft + 1.0f;
    if (frac < 0.5f) return ft;
    return (t & 1) ? ft + 1.0f : ft;
}

constexpr TabPart make_part(int part) {
    TabPart tp{};
    for (int i = 0; i < 4096; i++) {
        int idx = part * 4096 + i;
        float qmax = (float)(idx >> 8);
        float qmin = (float)(idx & 255);
        float vmax = qmax * (1.0f / 255.0f);
        float vmin = qmin * (1.0f / 255.0f);
        float l    = (vmax + vmin) * 0.5f;
        float diff = vmax - vmin;
        float denom = (l < 0.5f) ? (vmax + vmin) : ((2.0f - vmax) - vmin);
        float dmax  = (denom > 1e-12f) ? denom : 1e-12f;
        float s     = (diff > 0.0f) ? (diff / dmax) : 0.0f;
        float L = crint_nn(l * 255.0f);
        float S = crint_nn(s * 255.0f);
        if (L > 255.0f) L = 255.0f;  if (L < 0.0f) L = 0.0f;
        if (S > 255.0f) S = 255.0f;  if (S < 0.0f) S = 0.0f;
        tp.v[i] = (unsigned short)((int)L | ((int)S << 8));
    }
    return tp;
}

__device__ const TabPart g_tab16[16] = {
    make_part(0),  make_part(1),  make_part(2),  make_part(3),
    make_part(4),  make_part(5),  make_part(6),  make_part(7),
    make_part(8),  make_part(9),  make_part(10), make_part(11),
    make_part(12), make_part(13), make_part(14), make_part(15)
};

// ---------------------------------------------------------------------------
// Compile-time hue-weight table: channel = p1 + (p2-p1) * w(H8), with the
// w==1.0f sentinel meaning "return p2 directly" (the hh in [1,3) branch).
// Sentinel is unambiguous: hh==3.0 exactly is impossible (hi=180 gives
// fmul(180, fl(1/60)) = 3.0000002), and the hh<1 branch gives w<1.
// ---------------------------------------------------------------------------
struct alignas(16) W4 { float r, g, b, pad; };
struct HueTab { W4 v[256]; };

constexpr float hue_w(int hi) {
    int m = hi;                 // mod 360 for integer hi in [-120, 630]
    if (m < 0)    m += 360;
    if (m >= 360) m -= 360;
    float hh = (float)m * (1.0f / 60.0f);   // correctly-rounded constexpr mul
    if (hh < 1.0f) return hh;
    if (hh < 3.0f) return 1.0f;             // sentinel: return p2
    if (hh < 4.0f) return 4.0f - hh;        // correctly-rounded constexpr sub
    return 0.0f;
}

constexpr HueTab make_hue() {
    HueTab t{};
    for (int H8 = 0; H8 < 256; H8++) {
        int hi = H8 * 2;
        t.v[H8].r   = hue_w(hi + 120);
        t.v[H8].g   = hue_w(hi);
        t.v[H8].b   = hue_w(hi - 120);
        t.v[H8].pad = 0.0f;
    }
    return t;
}

__device__ const HueTab g_hueW = make_hue();

// IEEE ops, no FMA contraction (match XLA elementwise emission)
__device__ __forceinline__ float fdiv(float a, float b) { return __fdiv_rn(a, b); }
__device__ __forceinline__ float fmul(float a, float b) { return __fmul_rn(a, b); }
__device__ __forceinline__ float fadd(float a, float b) { return __fadd_rn(a, b); }
__device__ __forceinline__ float fsub(float a, float b) { return __fsub_rn(a, b); }

// ---------------------------------------------------------------------------
__device__ __forceinline__ unsigned hls_pixel(float rq, float gq, float bq, int* L8out)
{
    // inputs already clip(floor(v),0,255): exact small integers in float
    float qmaxf = fmaxf(fmaxf(rq, gq), bq);   // scaling is monotone-injective
    float qminf = fminf(fminf(rq, gq), bq);

    const unsigned short* tab = reinterpret_cast<const unsigned short*>(g_tab16);
    unsigned ls = __ldg(&tab[((int)qmaxf << 8) | (int)qminf]);
    int L8 = ls & 255, S8 = ls >> 8;

    float r  = fmul(rq, INV255);
    float g  = fmul(gq, INV255);
    float bl = fmul(bq, INV255);
    // safe = fmaxf(diff,1e-12) == diff whenever diff > 0 (min diff ~0.0039)
    float safe = fsub(fmul(qmaxf, INV255), fmul(qminf, INV255));

    const bool isr = (rq == qmaxf);
    const bool isg = (gq == qmaxf);
    float num = isr ? fsub(g, bl) : (isg ? fsub(bl, r) : fsub(r, g));
    float off = isr ? 0.f : (isg ? 120.f : 240.f);
    // gray pixels: 0/0 = NaN, selected away (reference forces h=0 when diff<=0)
    float h = (qmaxf > qminf) ? fadd(off, fdiv(fmul(60.f, num), safe)) : 0.f;
    if (h < 0.f) h = fadd(h, 360.f);

    int H8 = (int)fminf(fmaxf(rintf(fmul(h, 0.5f)), 0.f), 255.f);
    *L8out = L8;
    return (unsigned)H8 | ((unsigned)L8 << 8) | ((unsigned)S8 << 16);
}

// ---------------------------------------------------------------------------
// Kernel 1: quantize + RGB->HLS (u8) + per-tile histogram + clip/scan -> LUT.
// One block per tile. float4 streaming loads, uint4 packed HLS stores.
// ---------------------------------------------------------------------------
__global__ __launch_bounds__(256) void k1_hls_hist_lut(const float* __restrict__ img)
{
    __shared__ int hist[NBINS];
    const int tid = threadIdx.x;
    hist[tid] = 0;
    __syncthreads();

    const int gb = blockIdx.x;            // global tile id: b*64 + ty*8 + tx
    const int b  = gb >> 6;
    const int t  = gb & 63;
    const int ty = t >> 3, tx = t & 7;

    const float4* rp = reinterpret_cast<const float4*>(img + (size_t)b * 3 * PLANE);
    const float4* gp = rp + PLANE / 4;
    const float4* bp = gp + PLANE / 4;
    uint4* hlsp = reinterpret_cast<uint4*>(g_hls) + (size_t)b * (PLANE / 4);

    const int fv   = tid & 15;             // float4 index within tile row (16 per row)
    const int row0 = tid >> 4;             // 0..15

    #pragma unroll
    for (int pass = 0; pass < 4; pass++) {
        const int row  = row0 + pass * 16;
        const int y    = ty * TSZ + row;
        const int idx4 = y * (IMG_W / 4) + tx * (TSZ / 4) + fv;

        float4 r4 = __ldcs(&rp[idx4]);     // streaming: don't evict the table
        float4 g4 = __ldcs(&gp[idx4]);
        float4 b4 = __ldcs(&bp[idx4]);

        // quantize: clip(floor(v), 0, 255)
        r4.x = fminf(fmaxf(floorf(r4.x), 0.f), 255.f);
        r4.y = fminf(fmaxf(floorf(r4.y), 0.f), 255.f);
        r4.z = fminf(fmaxf(floorf(r4.z), 0.f), 255.f);
        r4.w = fminf(fmaxf(floorf(r4.w), 0.f), 255.f);
        g4.x = fminf(fmaxf(floorf(g4.x), 0.f), 255.f);
        g4.y = fminf(fmaxf(floorf(g4.y), 0.f), 255.f);
        g4.z = fminf(fmaxf(floorf(g4.z), 0.f), 255.f);
        g4.w = fminf(fmaxf(floorf(g4.w), 0.f), 255.f);
        b4.x = fminf(fmaxf(floorf(b4.x), 0.f), 255.f);
        b4.y = fminf(fmaxf(floorf(b4.y), 0.f), 255.f);
        b4.z = fminf(fmaxf(floorf(b4.z), 0.f), 255.f);
        b4.w = fminf(fmaxf(floorf(b4.w), 0.f), 255.f);

        int L0, L1, L2, L3;
        uint4 o;
        o.x = hls_pixel(r4.x, g4.x, b4.x, &L0);
        o.y = hls_pixel(r4.y, g4.y, b4.y, &L1);
        o.z = hls_pixel(r4.z, g4.z, b4.z, &L2);
        o.w = hls_pixel(r4.w, g4.w, b4.w, &L3);

        atomicAdd(&hist[L0], 1);
        atomicAdd(&hist[L1], 1);
        atomicAdd(&hist[L2], 1);
        atomicAdd(&hist[L3], 1);

        __stcs(&hlsp[idx4], o);
    }
    __syncthreads();

    // ---- fused: clip + excess redistribution + scan -> LUT ----
    int h = hist[tid];
    __syncthreads();

    hist[tid] = max(h - CLIPV, 0);
    __syncthreads();
    for (int off = 128; off > 0; off >>= 1) {
        if (tid < off) hist[tid] += hist[tid + off];
        __syncthreads();
    }
    const int excess = hist[0];
    __syncthreads();

    h = min(h, CLIPV) + excess / NBINS;
    const int residual = excess % NBINS;
    const int step = max(NBINS / max(residual, 1), 1);
    if (residual > 0 && (tid % step) == 0 && (tid / step) < residual) h += 1;

    // inclusive scan (Hillis–Steele)
    hist[tid] = h;
    __syncthreads();
    for (int off = 1; off < NBINS; off <<= 1) {
        int v = (tid >= off) ? hist[tid - off] : 0;
        __syncthreads();
        hist[tid] += v;
        __syncthreads();
    }

    float lv = rintf(fmul((float)hist[tid], 255.0f / 4096.0f));
    g_lut[gb * NBINS + tid] = (unsigned char)fminf(fmaxf(lv, 0.f), 255.f);
}

// ---------------------------------------------------------------------------
// Kernel 3: bilinear LUT interp (smem-staged LUTs + hue-weight table) +
// HLS->RGB, 4 px / thread. Each block = 2 image rows (1024 px); an
// (even,odd) row pair shares one (ty1,ty2) pair -> 16 LUTs = 4 KB staged.
// ---------------------------------------------------------------------------
__global__ __launch_bounds__(256) void k3_apply(float* __restrict__ out)
{
    __shared__ unsigned char lutS[4096];   // [2 rows][8 tiles][256 bins]
    __shared__ float4        hueS[256];    // hue weights (w_r, w_g, w_b)
    const int blk  = blockIdx.x;
    const int b    = blk >> 8;             // 256 blocks per image
    const int rem0 = (blk & 255) << 10;    // segment start (2 rows)
    const int tid  = threadIdx.x;
    const int y0   = rem0 >> 9;            // even row

    const int ty1s = (y0 - 32) >> 6;
    const int ty1  = max(ty1s, 0);
    const int ty2  = min(ty1s + 1, TILES - 1);

    {   // cooperative stage: 1 coalesced uint4 each for LUTs + hue table
        const int trow = (tid < 128) ? ty1 : ty2;
        const unsigned char* gsrc = g_lut + b * (TILES * TILES * NBINS)
                                  + (trow << 11) + ((tid & 127) << 4);
        reinterpret_cast<uint4*>(lutS)[tid] = *reinterpret_cast<const uint4*>(gsrc);
        hueS[tid] = reinterpret_cast<const float4*>(&g_hueW)[tid];
    }
    __syncthreads();

    const int y   = y0 + (tid >> 7);        // threads 0-127: row y0; 128-255: y0+1
    const int wy1 = (y - 32) & 63;          // ya * 64 (exact)
    const int wy0 = 64 - wy1;
    const int x0  = (tid << 2) & 511;
    const int rem = rem0 + tid * 4;

    const uint4 hls4 = __ldcs(reinterpret_cast<const uint4*>(&g_hls[(size_t)b * PLANE + rem]));
    const unsigned vals[4] = { hls4.x, hls4.y, hls4.z, hls4.w };

    float ro[4], go[4], bo[4];
    #pragma unroll
    for (int j = 0; j < 4; j++) {
        const unsigned pk = vals[j];
        const int H8 = pk & 255, L8 = (pk >> 8) & 255, S8 = (pk >> 16) & 255;

        const int xm   = x0 + j - 32;
        const int tx1s = xm >> 6;
        const int wx1  = xm & 63;
        const int wx0  = 64 - wx1;
        const int tx1  = max(tx1s, 0);
        const int tx2  = min(tx1s + 1, TILES - 1);

        const int c1 = (tx1 << 8) + L8;
        const int c2 = (tx2 << 8) + L8;
        const int g00 = lutS[c1];
        const int g01 = lutS[c2];
        const int g10 = lutS[2048 + c1];
        const int g11 = lutS[2048 + c2];

        // sum/4096 == fp32 reference bilinear exactly; sum < 2^21 so the
        // cvt + mul-by-2^-12 are exact and rintf gives half-even ties.
        const int sum = (g00 * wx0 + g01 * wx1) * wy0 + (g10 * wx0 + g11 * wx1) * wy1;
        const float Lnewf = rintf((float)sum * (1.0f / 4096.0f));

        // HLS -> RGB (reciprocal-mul for /255, no FMA contraction)
        float l  = fmul(Lnewf, INV255);
        float s  = fmul((float)S8, INV255);
        float p2 = (l <= 0.5f) ? fmul(l, fadd(1.f, s))
                               : fsub(fadd(l, s), fmul(l, s));
        float p1 = fsub(fmul(2.f, l), p2);
        float d  = fsub(p2, p1);

        const float4 w4 = hueS[H8];
        float r  = (w4.x == 1.0f) ? p2 : fadd(p1, fmul(d, w4.x));
        float g  = (w4.y == 1.0f) ? p2 : fadd(p1, fmul(d, w4.y));
        float bb = (w4.z == 1.0f) ? p2 : fadd(p1, fmul(d, w4.z));
        if (S8 == 0) { r = l; g = l; bb = l; }

        // outputs provably in [0,255] after rint -> clip is a no-op
        ro[j] = rintf(fmul(r,  255.f));
        go[j] = rintf(fmul(g,  255.f));
        bo[j] = rintf(fmul(bb, 255.f));
    }

    float* op = out + (size_t)b * 3 * PLANE + rem;
    *reinterpret_cast<float4*>(op)             = make_float4(ro[0], ro[1], ro[2], ro[3]);
    *reinterpret_cast<float4*>(op + PLANE)     = make_float4(go[0], go[1], go[2], go[3]);
    *reinterpret_cast<float4*>(op + 2 * PLANE) = make_float4(bo[0], bo[1], bo[2], bo[3]);
}

// ---------------------------------------------------------------------------
extern "C" void kernel_launch(void* const* d_in, const int* in_sizes, int n_in,
                              void* d_out, int out_size)
{
    (void)in_sizes; (void)n_in; (void)out_size;
    const float* img = (const float*)d_in[0];
    float* out = (float*)d_out;

    k1_hls_hist_lut<<<NT, 256>>>(img);
    k3_apply<<<BATCH * 256, 256>>>(out);
}